// round 7
// baseline (speedup 1.0000x reference)
#include <cuda_runtime.h>
#include <cuda_bf16.h>
#include <cstdint>

// ---------------------------------------------------------------------------
// Problem constants
// ---------------------------------------------------------------------------
#define VOCAB 50257
#define DIM   768
#define VPAD  50304            // ceil(VOCAB/128)*128 = 393*128
#define NTILE 6                // 768 / 128
#define NPAIRS_T 21            // upper-triangle 128x128 tiles (mi<=ni)
#define KSPLIT 7               // split-K -> 21*7 = 147 CTAs (one wave on 148 SMs)
#define EPS_F 1.1920929e-7f    // jnp.finfo(float32).eps

#define KC 64                  // K elements per pipeline stage
#define KCHUNKS (VPAD / KC)    // 786
#define STAGE_BYTES 32768      // A tile 16KB + B tile 16KB (128 rows x 128B each)
#define NSTAGES 4
#define SMEM_K3 (NSTAGES * STAGE_BYTES)

// ---------------------------------------------------------------------------
// Device scratch (allocation-free: __device__ globals)
// ---------------------------------------------------------------------------
__device__ __nv_bfloat16 g_Wt[(size_t)DIM * VPAD];  // Wn^T, bf16, dim-major, zero-padded K
__device__ float  g_Scale[VOCAB];
__device__ float  g_Diag[VOCAB];
__device__ float  g_G[DIM * DIM];                    // Gram accumulator (upper tiles)
__device__ double g_acc[2];                          // [0]=total_sq, [1]=diag_sq

// ---------------------------------------------------------------------------
// PTX helpers (family-portable: cp.async / ldmatrix / mma.sync only)
// ---------------------------------------------------------------------------
__device__ __forceinline__ uint32_t smem_to_u32(const void* p) {
    uint32_t a;
    asm("{ .reg .u64 t; cvta.to.shared.u64 t, %1; cvt.u32.u64 %0, t; }" : "=r"(a) : "l"(p));
    return a;
}

__device__ __forceinline__ void cp_async16(uint32_t dst, const void* src) {
    asm volatile("cp.async.cg.shared.global [%0], [%1], 16;" :: "r"(dst), "l"(src));
}

#define LDSM_X4(r, addr) \
    asm volatile("ldmatrix.sync.aligned.m8n8.x4.shared.b16 {%0,%1,%2,%3}, [%4];" \
        : "=r"((r)[0]), "=r"((r)[1]), "=r"((r)[2]), "=r"((r)[3]) : "r"(addr))

__device__ __forceinline__ void mma16816(float* c, const uint32_t* a, uint32_t b0, uint32_t b1) {
    asm volatile(
        "mma.sync.aligned.m16n8k16.row.col.f32.bf16.bf16.f32 "
        "{%0,%1,%2,%3}, {%4,%5,%6,%7}, {%8,%9}, {%0,%1,%2,%3};"
        : "+f"(c[0]), "+f"(c[1]), "+f"(c[2]), "+f"(c[3])
        : "r"(a[0]), "r"(a[1]), "r"(a[2]), "r"(a[3]), "r"(b0), "r"(b1));
}

// SW128 swizzle for 128-byte rows: XOR bits[6:4] with bits[9:7]
__device__ __forceinline__ uint32_t swz(uint32_t off) { return off ^ ((off >> 3) & 0x70); }

// ---------------------------------------------------------------------------
// Kernel 0: zero scratch (graph-capturable replacement for memset)
// ---------------------------------------------------------------------------
__global__ void zero_kernel() {
    int idx = blockIdx.x * blockDim.x + threadIdx.x;
    if (idx < DIM * DIM) g_G[idx] = 0.0f;
    if (idx < 2) g_acc[idx] = 0.0;
}

// ---------------------------------------------------------------------------
// Kernel 1: per-row sum of squares -> scale (rsqrt) and diag (= ||wn||^2)
// ---------------------------------------------------------------------------
__global__ void rowstats_kernel(const float* __restrict__ W) {
    int v = blockIdx.x;
    const float* row = W + (size_t)v * DIM;
    float s = 0.0f;
    #pragma unroll
    for (int i = 0; i < 3; i++) {
        float x = row[threadIdx.x + i * 256];
        s += x * x;
    }
    #pragma unroll
    for (int off = 16; off; off >>= 1) s += __shfl_xor_sync(0xffffffffu, s, off);
    __shared__ float ws[8];
    if ((threadIdx.x & 31) == 0) ws[threadIdx.x >> 5] = s;
    __syncthreads();
    if (threadIdx.x == 0) {
        float tot = 0.0f;
        #pragma unroll
        for (int i = 0; i < 8; i++) tot += ws[i];
        float m = tot * (1.0f / DIM);
        g_Scale[v] = rsqrtf(m + EPS_F);
        g_Diag[v]  = tot / (m + EPS_F);   // = ||wn_v||^2
    }
}

// ---------------------------------------------------------------------------
// Kernel 2: Wn -> bf16, transposed to dim-major Wt[768][VPAD] (K-contiguous
// for the GEMM). Pads v >= VOCAB with zeros (zero K-rows contribute nothing).
// ---------------------------------------------------------------------------
__global__ void transpose_kernel(const float* __restrict__ W) {
    __shared__ __align__(16) __nv_bfloat16 st[128][136];  // [d_local][v_local], padded
    int d0 = blockIdx.x * 128;
    int v0 = blockIdx.y * 128;
    int tid = threadIdx.x;
    int lane = tid & 31;
    int wsub = tid >> 5;

    #pragma unroll
    for (int p = 0; p < 16; p++) {
        int vl = p * 8 + wsub;
        int v = v0 + vl;
        float4 val = make_float4(0.f, 0.f, 0.f, 0.f);
        float sc = 0.0f;
        if (v < VOCAB) {
            val = *(const float4*)(W + (size_t)v * DIM + d0 + lane * 4);
            sc = g_Scale[v];
        }
        int d = lane * 4;
        st[d + 0][vl] = __float2bfloat16(val.x * sc);
        st[d + 1][vl] = __float2bfloat16(val.y * sc);
        st[d + 2][vl] = __float2bfloat16(val.z * sc);
        st[d + 3][vl] = __float2bfloat16(val.w * sc);
    }
    __syncthreads();
    #pragma unroll
    for (int q = 0; q < 8; q++) {
        int idx = q * 256 + tid;
        int dl = idx >> 4;
        int c  = idx & 15;
        uint4 val = *(const uint4*)&st[dl][c * 8];
        *(uint4*)(&g_Wt[(size_t)(d0 + dl) * VPAD + v0 + c * 8]) = val;
    }
}

// ---------------------------------------------------------------------------
// Kernel 3: bf16 Gram GEMM via mma.sync (m16n8k16), 4-stage cp.async pipeline.
// CTA: one 128x128 output tile (mi<=ni) x one K-split. 8 warps, 64x32 each.
// A tile = rows of Wt [m, k]; B tile = rows of Wt [n, k] (n-major = col-major
// k x n, so ldmatrix WITHOUT .trans feeds mma row.col directly).
// ---------------------------------------------------------------------------
__global__ void __launch_bounds__(256, 1) gram_kernel() {
    extern __shared__ char smem[];
    uint32_t sbase = smem_to_u32(smem);
    int tid = threadIdx.x;
    int wid = tid >> 5;
    int lane = tid & 31;

    // decode (mi, ni) with mi <= ni, and K split range
    int t = blockIdx.x % NPAIRS_T;
    int split = blockIdx.x / NPAIRS_T;
    int mi = 0;
    while (t >= NTILE - mi) { t -= NTILE - mi; mi++; }
    int ni = mi + t;
    int c0 = (split * KCHUNKS) / KSPLIT;
    int c1 = ((split + 1) * KCHUNKS) / KSPLIT;
    int nk = c1 - c0;

    const __nv_bfloat16* Abase = g_Wt + (size_t)(mi * 128) * VPAD;
    const __nv_bfloat16* Bbase = g_Wt + (size_t)(ni * 128) * VPAD;

    // cp.async thread assignment (same every stage)
    int ld_row = tid >> 3;          // 0..31 (+32 per i-iter)
    int ld_ch  = tid & 7;           // 16B chunk in 128B row

    float acc[4][4][4];
    #pragma unroll
    for (int a = 0; a < 4; a++)
        #pragma unroll
        for (int b = 0; b < 4; b++)
            #pragma unroll
            for (int c = 0; c < 4; c++) acc[a][b][c] = 0.0f;

    int warp_m = wid >> 2;          // 0..1
    int warp_n = wid & 3;           // 0..3
    int mbase = warp_m * 64;
    int nbase = warp_n * 32;

    // prologue: fill 3 stages
    #pragma unroll 1
    for (int s = 0; s < 3; s++) {
        if (s < nk) {
            uint32_t stA = sbase + s * STAGE_BYTES;
            uint32_t stB = stA + 16384;
            size_t kof = (size_t)(c0 + s) * KC + ld_ch * 8;
            #pragma unroll
            for (int i = 0; i < 4; i++) {
                int row = ld_row + i * 32;
                uint32_t d = swz((uint32_t)row * 128 + ld_ch * 16);
                cp_async16(stA + d, Abase + (size_t)row * VPAD + kof);
                cp_async16(stB + d, Bbase + (size_t)row * VPAD + kof);
            }
        }
        asm volatile("cp.async.commit_group;");
    }

    #pragma unroll 1
    for (int it = 0; it < nk; it++) {
        // wait for stage `it` (keep later stages in flight)
        int committed = (it + 3 < nk) ? (it + 3) : nk;
        int allow = committed - it - 1;
        if (allow >= 2)      asm volatile("cp.async.wait_group 2;");
        else if (allow == 1) asm volatile("cp.async.wait_group 1;");
        else                 asm volatile("cp.async.wait_group 0;");
        __syncthreads();

        uint32_t stA = sbase + (it & 3) * STAGE_BYTES;
        uint32_t stB = stA + 16384;

        #pragma unroll
        for (int ks = 0; ks < 4; ks++) {
            uint32_t a[4][4];
            int sub = lane >> 3;       // which 8x8 matrix this lane addresses
            int r8  = lane & 7;
            #pragma unroll
            for (int mt = 0; mt < 4; mt++) {
                int row = mbase + mt * 16 + (sub & 1) * 8 + r8;
                uint32_t addr = stA + swz((uint32_t)row * 128 + ks * 32 + (sub >> 1) * 16);
                LDSM_X4(a[mt], addr);
            }
            uint32_t b[2][4];
            #pragma unroll
            for (int np = 0; np < 2; np++) {
                int row = nbase + np * 16 + (sub >> 1) * 8 + r8;
                uint32_t addr = stB + swz((uint32_t)row * 128 + ks * 32 + (sub & 1) * 16);
                LDSM_X4(b[np], addr);
            }
            #pragma unroll
            for (int mt = 0; mt < 4; mt++)
                #pragma unroll
                for (int nt = 0; nt < 4; nt++)
                    mma16816(acc[mt][nt], a[mt],
                             b[nt >> 1][(nt & 1) * 2], b[nt >> 1][(nt & 1) * 2 + 1]);
        }

        // prefetch stage it+3
        if (it + 3 < nk) {
            int s = it + 3;
            uint32_t pA = sbase + (s & 3) * STAGE_BYTES;
            uint32_t pB = pA + 16384;
            size_t kof = (size_t)(c0 + s) * KC + ld_ch * 8;
            #pragma unroll
            for (int i = 0; i < 4; i++) {
                int row = ld_row + i * 32;
                uint32_t d = swz((uint32_t)row * 128 + ld_ch * 16);
                cp_async16(pA + d, Abase + (size_t)row * VPAD + kof);
                cp_async16(pB + d, Bbase + (size_t)row * VPAD + kof);
            }
            asm volatile("cp.async.commit_group;");
        }
    }

    // epilogue: merge split-K partials into g_G
    int g = lane >> 2;
    int tt = lane & 3;
    #pragma unroll
    for (int mt = 0; mt < 4; mt++) {
        int m = mi * 128 + mbase + mt * 16 + g;
        #pragma unroll
        for (int nt = 0; nt < 4; nt++) {
            int n = ni * 128 + nbase + nt * 8 + tt * 2;
            float* p0 = g_G + (size_t)m * DIM + n;
            float* p1 = g_G + (size_t)(m + 8) * DIM + n;
            atomicAdd(p0 + 0, acc[mt][nt][0]);
            atomicAdd(p0 + 1, acc[mt][nt][1]);
            atomicAdd(p1 + 0, acc[mt][nt][2]);
            atomicAdd(p1 + 1, acc[mt][nt][3]);
        }
    }
}

// ---------------------------------------------------------------------------
// Kernel 4: total_sq = sum over 768x768 of w*G^2 (w=2 for off-diagonal tiles;
// lower tiles are zero so they contribute nothing), diag_sq = sum diag^2
// ---------------------------------------------------------------------------
__global__ void reduce_kernel() {
    const int n1 = DIM * DIM;
    const int tot = n1 + VOCAB;
    double accT = 0.0, accD = 0.0;
    for (int idx = blockIdx.x * 256 + threadIdx.x; idx < tot; idx += gridDim.x * 256) {
        if (idx < n1) {
            int i = idx / DIM;
            int j = idx - i * DIM;
            double g = (double)g_G[idx];
            double w = ((i >> 7) == (j >> 7)) ? 1.0 : 2.0;
            accT += w * g * g;
        } else {
            double d = (double)g_Diag[idx - n1];
            accD += d * d;
        }
    }
    #pragma unroll
    for (int off = 16; off; off >>= 1) {
        accT += __shfl_xor_sync(0xffffffffu, accT, off);
        accD += __shfl_xor_sync(0xffffffffu, accD, off);
    }
    __shared__ double sT[8], sD[8];
    if ((threadIdx.x & 31) == 0) { sT[threadIdx.x >> 5] = accT; sD[threadIdx.x >> 5] = accD; }
    __syncthreads();
    if (threadIdx.x == 0) {
        double tT = 0.0, tD = 0.0;
        #pragma unroll
        for (int i = 0; i < 8; i++) { tT += sT[i]; tD += sD[i]; }
        atomicAdd(&g_acc[0], tT);
        atomicAdd(&g_acc[1], tD);
    }
}

// ---------------------------------------------------------------------------
// Kernel 5: finalize scalar
// ---------------------------------------------------------------------------
__global__ void finalize_kernel(float* out) {
    double n_pairs = (double)VOCAB * (double)(VOCAB - 1) * 0.5;
    out[0] = (float)((g_acc[0] - g_acc[1]) * 0.5 / n_pairs);
}

// ---------------------------------------------------------------------------
// Launch
// ---------------------------------------------------------------------------
extern "C" void kernel_launch(void* const* d_in, const int* in_sizes, int n_in,
                              void* d_out, int out_size) {
    (void)in_sizes; (void)n_in; (void)out_size;
    const float* W = (const float*)d_in[0];
    float* out = (float*)d_out;

    cudaFuncSetAttribute(gram_kernel, cudaFuncAttributeMaxDynamicSharedMemorySize, SMEM_K3);

    zero_kernel<<<(DIM * DIM + 255) / 256, 256>>>();
    rowstats_kernel<<<VOCAB, 256>>>(W);
    dim3 g2(NTILE, VPAD / 128);
    transpose_kernel<<<g2, 256>>>(W);
    gram_kernel<<<NPAIRS_T * KSPLIT, 256, SMEM_K3>>>();
    reduce_kernel<<<512, 256>>>();
    finalize_kernel<<<1, 1>>>(out);
}

// round 8
// speedup vs baseline: 1.4543x; 1.4543x over previous
#include <cuda_runtime.h>
#include <cuda_bf16.h>
#include <cstdint>

// ---------------------------------------------------------------------------
// Problem constants
// ---------------------------------------------------------------------------
#define VOCAB 50257
#define DIM   768
#define VPAD  50304            // ceil(VOCAB/128)*128 = 393*128
#define NTILE 6                // 768 / 128
#define NPAIRS_T 21            // upper-triangle 128x128 tiles (mi<=ni)
#define KSPLIT 7               // split-K -> 21*7 = 147 CTAs (one wave on 148 SMs)
#define EPS_F 1.1920929e-7f    // jnp.finfo(float32).eps

#define KC 64                  // K elements per pipeline stage
#define KCHUNKS (VPAD / KC)    // 786
#define STAGE_BYTES 32768      // A tile 16KB + B tile 16KB (128 rows x 128B each)
#define NSTAGES 4
#define SMEM_K3 (NSTAGES * STAGE_BYTES)

#define PREP_SMEM (32 * 768 * 4)   // 96KB fp32 staging

// ---------------------------------------------------------------------------
// Device scratch (allocation-free: __device__ globals)
// ---------------------------------------------------------------------------
__device__ __nv_bfloat16 g_Wt[(size_t)DIM * VPAD];  // Wn^T, bf16, dim-major, zero-padded K
__device__ float  g_Diag[VOCAB];
__device__ float  g_G[DIM * DIM];                    // Gram accumulator (upper tiles)
__device__ double g_acc[2];                          // [0]=total_sq, [1]=diag_sq

// ---------------------------------------------------------------------------
// PTX helpers (family-portable: cp.async / ldmatrix / mma.sync only)
// ---------------------------------------------------------------------------
__device__ __forceinline__ uint32_t smem_to_u32(const void* p) {
    uint32_t a;
    asm("{ .reg .u64 t; cvta.to.shared.u64 t, %1; cvt.u32.u64 %0, t; }" : "=r"(a) : "l"(p));
    return a;
}

__device__ __forceinline__ void cp_async16(uint32_t dst, const void* src) {
    asm volatile("cp.async.cg.shared.global [%0], [%1], 16;" :: "r"(dst), "l"(src));
}

#define LDSM_X4(r, addr) \
    asm volatile("ldmatrix.sync.aligned.m8n8.x4.shared.b16 {%0,%1,%2,%3}, [%4];" \
        : "=r"((r)[0]), "=r"((r)[1]), "=r"((r)[2]), "=r"((r)[3]) : "r"(addr))

__device__ __forceinline__ void mma16816(float* c, const uint32_t* a, uint32_t b0, uint32_t b1) {
    asm volatile(
        "mma.sync.aligned.m16n8k16.row.col.f32.bf16.bf16.f32 "
        "{%0,%1,%2,%3}, {%4,%5,%6,%7}, {%8,%9}, {%0,%1,%2,%3};"
        : "+f"(c[0]), "+f"(c[1]), "+f"(c[2]), "+f"(c[3])
        : "r"(a[0]), "r"(a[1]), "r"(a[2]), "r"(a[3]), "r"(b0), "r"(b1));
}

// SW128 swizzle for 128-byte rows: XOR bits[6:4] with bits[9:7]
__device__ __forceinline__ uint32_t swz(uint32_t off) { return off ^ ((off >> 3) & 0x70); }

// ---------------------------------------------------------------------------
// Kernel 1 (fused prep): zero scratch + row stats + scale + bf16 transpose.
// One block per 32 vocab rows. Full 32x768 fp32 row-chunk staged in smem with
// a 16B-chunk XOR swizzle -> conflict-free row-major stores AND transposed
// per-v float4 reads. Output Wt is dim-major (K-contiguous for the GEMM).
// ---------------------------------------------------------------------------
__global__ void __launch_bounds__(256) prep_kernel(const float* __restrict__ W) {
    extern __shared__ float s[];          // 32 rows x 192 float4-chunks, swizzled
    __shared__ float sscale[32];
    int tid = threadIdx.x;
    int wid = tid >> 5;
    int lane = tid & 31;
    int v0 = blockIdx.x * 32;

    // --- merged zero of g_G / g_acc (done before gram_kernel launches) ---
    {
        int zb = blockIdx.x * 384;
        int z0 = zb + tid;
        if (z0 < DIM * DIM) g_G[z0] = 0.0f;
        int z1 = zb + 256 + tid;
        if (tid < 128 && z1 < DIM * DIM) g_G[z1] = 0.0f;
        if (blockIdx.x == 0 && tid < 2) g_acc[tid] = 0.0;
    }

    // --- phase 1: each warp loads 4 rows, computes row sumsq, stages fp32 ---
    #pragma unroll
    for (int r = 0; r < 4; r++) {
        int vs = wid * 4 + r;
        int v = v0 + vs;
        float4 x[6];
        if (v < VOCAB) {
            const float4* rp = (const float4*)(W + (size_t)v * DIM);
            #pragma unroll
            for (int j = 0; j < 6; j++) x[j] = rp[lane + j * 32];
        } else {
            #pragma unroll
            for (int j = 0; j < 6; j++) x[j] = make_float4(0.f, 0.f, 0.f, 0.f);
        }
        float ssum = 0.0f;
        #pragma unroll
        for (int j = 0; j < 6; j++)
            ssum += x[j].x * x[j].x + x[j].y * x[j].y + x[j].z * x[j].z + x[j].w * x[j].w;
        #pragma unroll
        for (int off = 16; off; off >>= 1) ssum += __shfl_xor_sync(0xffffffffu, ssum, off);

        float4* sv = (float4*)s + vs * 192;
        #pragma unroll
        for (int j = 0; j < 6; j++)
            sv[(lane + j * 32) ^ vs] = x[j];   // XOR hits only low-5 bits of chunk

        if (lane == 0) {
            float m = ssum * (1.0f / DIM) + EPS_F;
            sscale[vs] = rsqrtf(m);
            if (v < VOCAB) g_Diag[v] = ssum / m;   // = ||wn_v||^2
        }
    }
    __syncthreads();

    // --- phase 2: transposed bf16 writes; lane <-> v, warp covers 24 chunks ---
    float sc = sscale[lane];
    const float4* sl = (const float4*)s + lane * 192;
    __nv_bfloat16* ocol = g_Wt + v0 + lane;
    #pragma unroll 4
    for (int c = 0; c < 24; c++) {
        int chunk = wid * 24 + c;
        float4 x = sl[chunk ^ lane];
        size_t d = (size_t)chunk * 4;
        ocol[(d + 0) * VPAD] = __float2bfloat16(x.x * sc);
        ocol[(d + 1) * VPAD] = __float2bfloat16(x.y * sc);
        ocol[(d + 2) * VPAD] = __float2bfloat16(x.z * sc);
        ocol[(d + 3) * VPAD] = __float2bfloat16(x.w * sc);
    }
}

// ---------------------------------------------------------------------------
// Kernel 2: bf16 Gram GEMM via mma.sync (m16n8k16), 4-stage cp.async pipeline,
// register double-buffered ldmatrix fragments.
// CTA: one 128x128 output tile (mi<=ni) x one K-split. 8 warps, 64x32 each.
// ---------------------------------------------------------------------------
__device__ __forceinline__ void load_frag_a(uint32_t stA, int mbase, int sub, int r8,
                                            int ks, uint32_t a[4][4]) {
    #pragma unroll
    for (int mt = 0; mt < 4; mt++) {
        int row = mbase + mt * 16 + (sub & 1) * 8 + r8;
        uint32_t addr = stA + swz((uint32_t)row * 128 + ks * 32 + (sub >> 1) * 16);
        LDSM_X4(a[mt], addr);
    }
}
__device__ __forceinline__ void load_frag_b(uint32_t stB, int nbase, int sub, int r8,
                                            int ks, uint32_t b[2][4]) {
    #pragma unroll
    for (int np = 0; np < 2; np++) {
        int row = nbase + np * 16 + (sub >> 1) * 8 + r8;
        uint32_t addr = stB + swz((uint32_t)row * 128 + ks * 32 + (sub & 1) * 16);
        LDSM_X4(b[np], addr);
    }
}

__global__ void __launch_bounds__(256, 1) gram_kernel() {
    extern __shared__ char smem[];
    uint32_t sbase = smem_to_u32(smem);
    int tid = threadIdx.x;
    int wid = tid >> 5;
    int lane = tid & 31;

    // decode (mi, ni) with mi <= ni, and K split range
    int t = blockIdx.x % NPAIRS_T;
    int split = blockIdx.x / NPAIRS_T;
    int mi = 0;
    while (t >= NTILE - mi) { t -= NTILE - mi; mi++; }
    int ni = mi + t;
    int c0 = (split * KCHUNKS) / KSPLIT;
    int c1 = ((split + 1) * KCHUNKS) / KSPLIT;
    int nk = c1 - c0;

    const __nv_bfloat16* Abase = g_Wt + (size_t)(mi * 128) * VPAD;
    const __nv_bfloat16* Bbase = g_Wt + (size_t)(ni * 128) * VPAD;

    int ld_row = tid >> 3;          // 0..31 (+32 per i-iter)
    int ld_ch  = tid & 7;           // 16B chunk in 128B row

    float acc[4][4][4];
    #pragma unroll
    for (int a = 0; a < 4; a++)
        #pragma unroll
        for (int b = 0; b < 4; b++)
            #pragma unroll
            for (int c = 0; c < 4; c++) acc[a][b][c] = 0.0f;

    int warp_m = wid >> 2;          // 0..1
    int warp_n = wid & 3;           // 0..3
    int mbase = warp_m * 64;
    int nbase = warp_n * 32;
    int sub = lane >> 3;
    int r8  = lane & 7;

    // prologue: fill 3 stages
    #pragma unroll 1
    for (int s = 0; s < 3; s++) {
        if (s < nk) {
            uint32_t stA = sbase + s * STAGE_BYTES;
            uint32_t stB = stA + 16384;
            size_t kof = (size_t)(c0 + s) * KC + ld_ch * 8;
            #pragma unroll
            for (int i = 0; i < 4; i++) {
                int row = ld_row + i * 32;
                uint32_t d = swz((uint32_t)row * 128 + ld_ch * 16);
                cp_async16(stA + d, Abase + (size_t)row * VPAD + kof);
                cp_async16(stB + d, Bbase + (size_t)row * VPAD + kof);
            }
        }
        asm volatile("cp.async.commit_group;");
    }

    #pragma unroll 1
    for (int it = 0; it < nk; it++) {
        int committed = (it + 3 < nk) ? (it + 3) : nk;
        int allow = committed - it - 1;
        if (allow >= 2)      asm volatile("cp.async.wait_group 2;");
        else if (allow == 1) asm volatile("cp.async.wait_group 1;");
        else                 asm volatile("cp.async.wait_group 0;");
        __syncthreads();

        uint32_t stA = sbase + (it & 3) * STAGE_BYTES;
        uint32_t stB = stA + 16384;

        // register double-buffered fragment pipeline across the 4 k-steps
        uint32_t afr[2][4][4], bfr[2][2][4];
        load_frag_a(stA, mbase, sub, r8, 0, afr[0]);
        load_frag_b(stB, nbase, sub, r8, 0, bfr[0]);
        #pragma unroll
        for (int ks = 0; ks < 4; ks++) {
            int cb = ks & 1, nb = cb ^ 1;
            if (ks < 3) {
                load_frag_a(stA, mbase, sub, r8, ks + 1, afr[nb]);
                load_frag_b(stB, nbase, sub, r8, ks + 1, bfr[nb]);
            }
            #pragma unroll
            for (int mt = 0; mt < 4; mt++)
                #pragma unroll
                for (int nt = 0; nt < 4; nt++)
                    mma16816(acc[mt][nt], afr[cb][mt],
                             bfr[cb][nt >> 1][(nt & 1) * 2],
                             bfr[cb][nt >> 1][(nt & 1) * 2 + 1]);
        }

        // prefetch stage it+3
        if (it + 3 < nk) {
            int s = it + 3;
            uint32_t pA = sbase + (s & 3) * STAGE_BYTES;
            uint32_t pB = pA + 16384;
            size_t kof = (size_t)(c0 + s) * KC + ld_ch * 8;
            #pragma unroll
            for (int i = 0; i < 4; i++) {
                int row = ld_row + i * 32;
                uint32_t d = swz((uint32_t)row * 128 + ld_ch * 16);
                cp_async16(pA + d, Abase + (size_t)row * VPAD + kof);
                cp_async16(pB + d, Bbase + (size_t)row * VPAD + kof);
            }
            asm volatile("cp.async.commit_group;");
        }
    }

    // epilogue: merge split-K partials into g_G
    int g = lane >> 2;
    int tt = lane & 3;
    #pragma unroll
    for (int mt = 0; mt < 4; mt++) {
        int m = mi * 128 + mbase + mt * 16 + g;
        #pragma unroll
        for (int nt = 0; nt < 4; nt++) {
            int n = ni * 128 + nbase + nt * 8 + tt * 2;
            float* p0 = g_G + (size_t)m * DIM + n;
            float* p1 = g_G + (size_t)(m + 8) * DIM + n;
            atomicAdd(p0 + 0, acc[mt][nt][0]);
            atomicAdd(p0 + 1, acc[mt][nt][1]);
            atomicAdd(p1 + 0, acc[mt][nt][2]);
            atomicAdd(p1 + 1, acc[mt][nt][3]);
        }
    }
}

// ---------------------------------------------------------------------------
// Kernel 3: total_sq = sum over 768x768 of w*G^2 (w=2 for off-diagonal tiles;
// lower tiles are zero so they contribute nothing), diag_sq = sum diag^2
// ---------------------------------------------------------------------------
__global__ void reduce_kernel() {
    const int n1 = DIM * DIM;
    const int tot = n1 + VOCAB;
    double accT = 0.0, accD = 0.0;
    for (int idx = blockIdx.x * 256 + threadIdx.x; idx < tot; idx += gridDim.x * 256) {
        if (idx < n1) {
            int i = idx / DIM;
            int j = idx - i * DIM;
            double g = (double)g_G[idx];
            double w = ((i >> 7) == (j >> 7)) ? 1.0 : 2.0;
            accT += w * g * g;
        } else {
            double d = (double)g_Diag[idx - n1];
            accD += d * d;
        }
    }
    #pragma unroll
    for (int off = 16; off; off >>= 1) {
        accT += __shfl_xor_sync(0xffffffffu, accT, off);
        accD += __shfl_xor_sync(0xffffffffu, accD, off);
    }
    __shared__ double sT[8], sD[8];
    if ((threadIdx.x & 31) == 0) { sT[threadIdx.x >> 5] = accT; sD[threadIdx.x >> 5] = accD; }
    __syncthreads();
    if (threadIdx.x == 0) {
        double tT = 0.0, tD = 0.0;
        #pragma unroll
        for (int i = 0; i < 8; i++) { tT += sT[i]; tD += sD[i]; }
        atomicAdd(&g_acc[0], tT);
        atomicAdd(&g_acc[1], tD);
    }
}

// ---------------------------------------------------------------------------
// Kernel 4: finalize scalar
// ---------------------------------------------------------------------------
__global__ void finalize_kernel(float* out) {
    double n_pairs = (double)VOCAB * (double)(VOCAB - 1) * 0.5;
    out[0] = (float)((g_acc[0] - g_acc[1]) * 0.5 / n_pairs);
}

// ---------------------------------------------------------------------------
// Launch
// ---------------------------------------------------------------------------
extern "C" void kernel_launch(void* const* d_in, const int* in_sizes, int n_in,
                              void* d_out, int out_size) {
    (void)in_sizes; (void)n_in; (void)out_size;
    const float* W = (const float*)d_in[0];
    float* out = (float*)d_out;

    cudaFuncSetAttribute(prep_kernel, cudaFuncAttributeMaxDynamicSharedMemorySize, PREP_SMEM);
    cudaFuncSetAttribute(gram_kernel, cudaFuncAttributeMaxDynamicSharedMemorySize, SMEM_K3);

    prep_kernel<<<VPAD / 32, 256, PREP_SMEM>>>(W);
    gram_kernel<<<NPAIRS_T * KSPLIT, 256, SMEM_K3>>>();
    reduce_kernel<<<512, 256>>>();
    finalize_kernel<<<1, 1>>>(out);
}

// round 9
// speedup vs baseline: 1.5950x; 1.0968x over previous
#include <cuda_runtime.h>
#include <cuda_bf16.h>
#include <cstdint>

// ---------------------------------------------------------------------------
// Problem constants
// ---------------------------------------------------------------------------
#define VOCAB 50257
#define DIM   768
#define VPAD  50304            // ceil(VOCAB/128)*128 = 393*128
#define NTILE 6                // 768 / 128
#define NPAIRS_T 21            // upper-triangle 128x128 tiles (mi<=ni)
#define KSPLIT 14              // split-K -> 21*14 = 294 CTAs (2 per SM)
#define EPS_F 1.1920929e-7f    // jnp.finfo(float32).eps

#define KC 64                  // K elements per pipeline stage
#define KCHUNKS (VPAD / KC)    // 786
#define STAGE_BYTES 32768      // A tile 16KB + B tile 16KB (128 rows x 128B each)
#define NSTAGES 3
#define SMEM_K3 (NSTAGES * STAGE_BYTES)   // 96KB -> 2 CTAs/SM

#define PREP_SMEM (32 * 768 * 4)   // 96KB fp32 staging

#define REDUCE_GRID 256

// ---------------------------------------------------------------------------
// Device scratch (allocation-free: __device__ globals)
// ---------------------------------------------------------------------------
__device__ __nv_bfloat16 g_Wt[(size_t)DIM * VPAD];  // Wn^T, bf16, dim-major, zero-padded K
__device__ float  g_Diag[VOCAB];
__device__ float  g_G[DIM * DIM];                    // Gram accumulator (upper tiles)
__device__ double g_acc[2];                          // [0]=total_sq, [1]=diag_sq
__device__ unsigned g_done;                          // last-block flag for fused finalize

// ---------------------------------------------------------------------------
// PTX helpers (family-portable: cp.async / ldmatrix / mma.sync only)
// ---------------------------------------------------------------------------
__device__ __forceinline__ uint32_t smem_to_u32(const void* p) {
    uint32_t a;
    asm("{ .reg .u64 t; cvta.to.shared.u64 t, %1; cvt.u32.u64 %0, t; }" : "=r"(a) : "l"(p));
    return a;
}

__device__ __forceinline__ void cp_async16(uint32_t dst, const void* src) {
    asm volatile("cp.async.cg.shared.global [%0], [%1], 16;" :: "r"(dst), "l"(src));
}

#define LDSM_X4(r, addr) \
    asm volatile("ldmatrix.sync.aligned.m8n8.x4.shared.b16 {%0,%1,%2,%3}, [%4];" \
        : "=r"((r)[0]), "=r"((r)[1]), "=r"((r)[2]), "=r"((r)[3]) : "r"(addr))

__device__ __forceinline__ void mma16816(float* c, const uint32_t* a, uint32_t b0, uint32_t b1) {
    asm volatile(
        "mma.sync.aligned.m16n8k16.row.col.f32.bf16.bf16.f32 "
        "{%0,%1,%2,%3}, {%4,%5,%6,%7}, {%8,%9}, {%0,%1,%2,%3};"
        : "+f"(c[0]), "+f"(c[1]), "+f"(c[2]), "+f"(c[3])
        : "r"(a[0]), "r"(a[1]), "r"(a[2]), "r"(a[3]), "r"(b0), "r"(b1));
}

// SW128 swizzle for 128-byte rows: XOR bits[6:4] with bits[9:7]
__device__ __forceinline__ uint32_t swz(uint32_t off) { return off ^ ((off >> 3) & 0x70); }

// ---------------------------------------------------------------------------
// Kernel 1 (fused prep): zero scratch + row stats + scale + bf16 transpose.
// One block per 32 vocab rows. Full 32x768 fp32 row-chunk staged in smem with
// a 16B-chunk XOR swizzle -> conflict-free row-major stores AND transposed
// per-v float4 reads. Output Wt is dim-major (K-contiguous for the GEMM).
// ---------------------------------------------------------------------------
__global__ void __launch_bounds__(256) prep_kernel(const float* __restrict__ W) {
    extern __shared__ float s[];          // 32 rows x 192 float4-chunks, swizzled
    __shared__ float sscale[32];
    int tid = threadIdx.x;
    int wid = tid >> 5;
    int lane = tid & 31;
    int v0 = blockIdx.x * 32;

    // --- merged zero of g_G / g_acc / g_done ---
    {
        int zb = blockIdx.x * 384;
        int z0 = zb + tid;
        if (z0 < DIM * DIM) g_G[z0] = 0.0f;
        int z1 = zb + 256 + tid;
        if (tid < 128 && z1 < DIM * DIM) g_G[z1] = 0.0f;
        if (blockIdx.x == 0 && tid < 2) g_acc[tid] = 0.0;
        if (blockIdx.x == 0 && tid == 2) g_done = 0u;
    }

    // --- phase 1: each warp loads 4 rows, computes row sumsq, stages fp32 ---
    #pragma unroll
    for (int r = 0; r < 4; r++) {
        int vs = wid * 4 + r;
        int v = v0 + vs;
        float4 x[6];
        if (v < VOCAB) {
            const float4* rp = (const float4*)(W + (size_t)v * DIM);
            #pragma unroll
            for (int j = 0; j < 6; j++) x[j] = rp[lane + j * 32];
        } else {
            #pragma unroll
            for (int j = 0; j < 6; j++) x[j] = make_float4(0.f, 0.f, 0.f, 0.f);
        }
        float ssum = 0.0f;
        #pragma unroll
        for (int j = 0; j < 6; j++)
            ssum += x[j].x * x[j].x + x[j].y * x[j].y + x[j].z * x[j].z + x[j].w * x[j].w;
        #pragma unroll
        for (int off = 16; off; off >>= 1) ssum += __shfl_xor_sync(0xffffffffu, ssum, off);

        float4* sv = (float4*)s + vs * 192;
        #pragma unroll
        for (int j = 0; j < 6; j++)
            sv[(lane + j * 32) ^ vs] = x[j];   // XOR hits only low-5 bits of chunk

        if (lane == 0) {
            float m = ssum * (1.0f / DIM) + EPS_F;
            sscale[vs] = rsqrtf(m);
            if (v < VOCAB) g_Diag[v] = ssum / m;   // = ||wn_v||^2
        }
    }
    __syncthreads();

    // --- phase 2: transposed bf16 writes; lane <-> v, warp covers 24 chunks ---
    float sc = sscale[lane];
    const float4* sl = (const float4*)s + lane * 192;
    __nv_bfloat16* ocol = g_Wt + v0 + lane;
    #pragma unroll 4
    for (int c = 0; c < 24; c++) {
        int chunk = wid * 24 + c;
        float4 x = sl[chunk ^ lane];
        size_t d = (size_t)chunk * 4;
        ocol[(d + 0) * VPAD] = __float2bfloat16(x.x * sc);
        ocol[(d + 1) * VPAD] = __float2bfloat16(x.y * sc);
        ocol[(d + 2) * VPAD] = __float2bfloat16(x.z * sc);
        ocol[(d + 3) * VPAD] = __float2bfloat16(x.w * sc);
    }
}

// ---------------------------------------------------------------------------
// Kernel 2: bf16 Gram GEMM via mma.sync (m16n8k16).
// 3-stage cp.async pipeline (prefetch distance 2), 96KB smem -> 2 CTAs/SM
// (16 warps/SM fill tensor-pipe bubbles). CTA: one 128x128 tile (mi<=ni) x
// one of 14 K-splits. 8 warps, 64x32 each, single-buffered fragments.
// ---------------------------------------------------------------------------
__global__ void __launch_bounds__(256, 2) gram_kernel() {
    extern __shared__ char smem[];
    uint32_t sbase = smem_to_u32(smem);
    int tid = threadIdx.x;
    int wid = tid >> 5;
    int lane = tid & 31;

    // decode (mi, ni) with mi <= ni, and K split range
    int t = blockIdx.x % NPAIRS_T;
    int split = blockIdx.x / NPAIRS_T;
    int mi = 0;
    while (t >= NTILE - mi) { t -= NTILE - mi; mi++; }
    int ni = mi + t;
    int c0 = (split * KCHUNKS) / KSPLIT;
    int c1 = ((split + 1) * KCHUNKS) / KSPLIT;
    int nk = c1 - c0;

    const __nv_bfloat16* Abase = g_Wt + (size_t)(mi * 128) * VPAD;
    const __nv_bfloat16* Bbase = g_Wt + (size_t)(ni * 128) * VPAD;

    int ld_row = tid >> 3;          // 0..31 (+32 per i-iter)
    int ld_ch  = tid & 7;           // 16B chunk in 128B row

    float acc[4][4][4];
    #pragma unroll
    for (int a = 0; a < 4; a++)
        #pragma unroll
        for (int b = 0; b < 4; b++)
            #pragma unroll
            for (int c = 0; c < 4; c++) acc[a][b][c] = 0.0f;

    int warp_m = wid >> 2;          // 0..1
    int warp_n = wid & 3;           // 0..3
    int mbase = warp_m * 64;
    int nbase = warp_n * 32;
    int sub = lane >> 3;
    int r8  = lane & 7;

    // per-warp LDSM base offsets (within a stage buffer)
    uint32_t a_off[4], b_off[2];
    #pragma unroll
    for (int mt = 0; mt < 4; mt++) {
        int row = mbase + mt * 16 + (sub & 1) * 8 + r8;
        a_off[mt] = (uint32_t)row * 128 + (sub >> 1) * 16;
    }
    #pragma unroll
    for (int np = 0; np < 2; np++) {
        int row = nbase + np * 16 + (sub >> 1) * 8 + r8;
        b_off[np] = (uint32_t)row * 128 + (sub & 1) * 16;
    }

    // prologue: fill 2 stages (prefetch distance 2)
    #pragma unroll 1
    for (int s = 0; s < 2; s++) {
        if (s < nk) {
            uint32_t stA = sbase + s * STAGE_BYTES;
            uint32_t stB = stA + 16384;
            size_t kof = (size_t)(c0 + s) * KC + ld_ch * 8;
            #pragma unroll
            for (int i = 0; i < 4; i++) {
                int row = ld_row + i * 32;
                uint32_t d = swz((uint32_t)row * 128 + ld_ch * 16);
                cp_async16(stA + d, Abase + (size_t)row * VPAD + kof);
                cp_async16(stB + d, Bbase + (size_t)row * VPAD + kof);
            }
        }
        asm volatile("cp.async.commit_group;");
    }

    int buf = 0;
    #pragma unroll 1
    for (int it = 0; it < nk; it++) {
        // commits so far = it + 2; stage `it` is complete once <=1 group pending
        asm volatile("cp.async.wait_group 1;");
        __syncthreads();

        uint32_t stA = sbase + buf * STAGE_BYTES;
        uint32_t stB = stA + 16384;

        #pragma unroll
        for (int ks = 0; ks < 4; ks++) {
            uint32_t a[4][4], b[2][4];
            uint32_t kofs = (uint32_t)ks * 32;
            #pragma unroll
            for (int mt = 0; mt < 4; mt++) LDSM_X4(a[mt], stA + swz(a_off[mt] + kofs));
            #pragma unroll
            for (int np = 0; np < 2; np++) LDSM_X4(b[np], stB + swz(b_off[np] + kofs));
            #pragma unroll
            for (int mt = 0; mt < 4; mt++)
                #pragma unroll
                for (int nt = 0; nt < 4; nt++)
                    mma16816(acc[mt][nt], a[mt],
                             b[nt >> 1][(nt & 1) * 2], b[nt >> 1][(nt & 1) * 2 + 1]);
        }

        // prefetch stage it+2 into buffer (it+2)%3 == (it-1)%3 (freed last iter)
        if (it + 2 < nk) {
            int s = it + 2;
            int pb = buf + 2; if (pb >= 3) pb -= 3;
            uint32_t pA = sbase + pb * STAGE_BYTES;
            uint32_t pB = pA + 16384;
            size_t kof = (size_t)(c0 + s) * KC + ld_ch * 8;
            #pragma unroll
            for (int i = 0; i < 4; i++) {
                int row = ld_row + i * 32;
                uint32_t d = swz((uint32_t)row * 128 + ld_ch * 16);
                cp_async16(pA + d, Abase + (size_t)row * VPAD + kof);
                cp_async16(pB + d, Bbase + (size_t)row * VPAD + kof);
            }
        }
        asm volatile("cp.async.commit_group;");
        if (++buf == 3) buf = 0;
    }

    // epilogue: merge split-K partials into g_G
    int g = lane >> 2;
    int tt = lane & 3;
    #pragma unroll
    for (int mt = 0; mt < 4; mt++) {
        int m = mi * 128 + mbase + mt * 16 + g;
        #pragma unroll
        for (int nt = 0; nt < 4; nt++) {
            int n = ni * 128 + nbase + nt * 8 + tt * 2;
            float* p0 = g_G + (size_t)m * DIM + n;
            float* p1 = g_G + (size_t)(m + 8) * DIM + n;
            atomicAdd(p0 + 0, acc[mt][nt][0]);
            atomicAdd(p0 + 1, acc[mt][nt][1]);
            atomicAdd(p1 + 0, acc[mt][nt][2]);
            atomicAdd(p1 + 1, acc[mt][nt][3]);
        }
    }
}

// ---------------------------------------------------------------------------
// Kernel 3 (fused reduce+finalize): total_sq = sum over 768x768 of w*G^2
// (w=2 for off-diagonal tiles; lower tiles are zero), diag_sq = sum diag^2.
// Last block finalizes the scalar output.
// ---------------------------------------------------------------------------
__global__ void reduce_kernel(float* __restrict__ out) {
    const int n1 = DIM * DIM;
    const int tot = n1 + VOCAB;
    double accT = 0.0, accD = 0.0;
    for (int idx = blockIdx.x * 256 + threadIdx.x; idx < tot; idx += REDUCE_GRID * 256) {
        if (idx < n1) {
            int i = idx / DIM;
            int j = idx - i * DIM;
            double g = (double)g_G[idx];
            double w = ((i >> 7) == (j >> 7)) ? 1.0 : 2.0;
            accT += w * g * g;
        } else {
            double d = (double)g_Diag[idx - n1];
            accD += d * d;
        }
    }
    #pragma unroll
    for (int off = 16; off; off >>= 1) {
        accT += __shfl_xor_sync(0xffffffffu, accT, off);
        accD += __shfl_xor_sync(0xffffffffu, accD, off);
    }
    __shared__ double sT[8], sD[8];
    __shared__ bool is_last;
    if ((threadIdx.x & 31) == 0) { sT[threadIdx.x >> 5] = accT; sD[threadIdx.x >> 5] = accD; }
    __syncthreads();
    if (threadIdx.x == 0) {
        double tT = 0.0, tD = 0.0;
        #pragma unroll
        for (int i = 0; i < 8; i++) { tT += sT[i]; tD += sD[i]; }
        atomicAdd(&g_acc[0], tT);
        atomicAdd(&g_acc[1], tD);
        __threadfence();
        unsigned prev = atomicAdd(&g_done, 1u);
        is_last = (prev == REDUCE_GRID - 1);
    }
    __syncthreads();
    if (is_last && threadIdx.x == 0) {
        double n_pairs = (double)VOCAB * (double)(VOCAB - 1) * 0.5;
        out[0] = (float)((g_acc[0] - g_acc[1]) * 0.5 / n_pairs);
    }
}

// ---------------------------------------------------------------------------
// Launch
// ---------------------------------------------------------------------------
extern "C" void kernel_launch(void* const* d_in, const int* in_sizes, int n_in,
                              void* d_out, int out_size) {
    (void)in_sizes; (void)n_in; (void)out_size;
    const float* W = (const float*)d_in[0];
    float* out = (float*)d_out;

    cudaFuncSetAttribute(prep_kernel, cudaFuncAttributeMaxDynamicSharedMemorySize, PREP_SMEM);
    cudaFuncSetAttribute(gram_kernel, cudaFuncAttributeMaxDynamicSharedMemorySize, SMEM_K3);

    prep_kernel<<<VPAD / 32, 256, PREP_SMEM>>>(W);
    gram_kernel<<<NPAIRS_T * KSPLIT, 256, SMEM_K3>>>();
    reduce_kernel<<<REDUCE_GRID, 256>>>(out);
}

// round 10
// speedup vs baseline: 1.6739x; 1.0495x over previous
#include <cuda_runtime.h>
#include <cuda_bf16.h>
#include <cstdint>

// ---------------------------------------------------------------------------
// Problem constants
// ---------------------------------------------------------------------------
#define VOCAB 50257
#define DIM   768
#define VPAD  50304            // ceil(VOCAB/128)*128 = 393*128
#define NTILE 6                // 768 / 128
#define NPAIRS_T 21            // upper-triangle 128x128 tiles (mi<=ni)
#define KSPLIT 14              // split-K -> 21*14 = 294 CTAs (2 per SM)
#define EPS_F 1.1920929e-7f    // jnp.finfo(float32).eps

#define KC 64                  // K elements per pipeline stage
#define KCHUNKS (VPAD / KC)    // 786
#define STAGE_BYTES 32768      // A tile 16KB + B tile 16KB (128 rows x 128B each)
#define NSTAGES 3
#define SMEM_K3 (NSTAGES * STAGE_BYTES)   // 96KB -> 2 CTAs/SM

#define PREP_SMEM (32 * 192 * 8)   // 48KB bf16 staging (32 rows x 192 uint2)

#define REDUCE_GRID 256

// ---------------------------------------------------------------------------
// Device scratch (allocation-free: __device__ globals)
// ---------------------------------------------------------------------------
__device__ __nv_bfloat16 g_Wt[(size_t)DIM * VPAD];  // Wn^T, bf16, dim-major, zero-padded K
__device__ float  g_Diag[VOCAB];
__device__ float  g_G[DIM * DIM];                    // Gram accumulator (upper tiles)
__device__ double g_acc[2];                          // [0]=total_sq, [1]=diag_sq
__device__ unsigned g_done;                          // last-block flag for fused finalize

// ---------------------------------------------------------------------------
// PTX helpers (family-portable: cp.async / ldmatrix / mma.sync only)
// ---------------------------------------------------------------------------
__device__ __forceinline__ uint32_t smem_to_u32(const void* p) {
    uint32_t a;
    asm("{ .reg .u64 t; cvta.to.shared.u64 t, %1; cvt.u32.u64 %0, t; }" : "=r"(a) : "l"(p));
    return a;
}

__device__ __forceinline__ void cp_async16(uint32_t dst, const void* src) {
    asm volatile("cp.async.cg.shared.global [%0], [%1], 16;" :: "r"(dst), "l"(src));
}

#define LDSM_X4(r, addr) \
    asm volatile("ldmatrix.sync.aligned.m8n8.x4.shared.b16 {%0,%1,%2,%3}, [%4];" \
        : "=r"((r)[0]), "=r"((r)[1]), "=r"((r)[2]), "=r"((r)[3]) : "r"(addr))

__device__ __forceinline__ void mma16816(float* c, const uint32_t* a, uint32_t b0, uint32_t b1) {
    asm volatile(
        "mma.sync.aligned.m16n8k16.row.col.f32.bf16.bf16.f32 "
        "{%0,%1,%2,%3}, {%4,%5,%6,%7}, {%8,%9}, {%0,%1,%2,%3};"
        : "+f"(c[0]), "+f"(c[1]), "+f"(c[2]), "+f"(c[3])
        : "r"(a[0]), "r"(a[1]), "r"(a[2]), "r"(a[3]), "r"(b0), "r"(b1));
}

// SW128 swizzle for 128-byte rows: XOR bits[6:4] with bits[9:7]
__device__ __forceinline__ uint32_t swz(uint32_t off) { return off ^ ((off >> 3) & 0x70); }

// ---------------------------------------------------------------------------
// Kernel 1 (fused prep): zero scratch + row stats + bf16 quantize + transpose.
// One block per 32 vocab rows. Rows staged in smem as *bf16* (48KB -> 4
// CTAs/SM) with an 8B-chunk XOR swizzle (conflict-free both phases). The
// fp32 row scale is applied during the transposed phase-2 read.
// ---------------------------------------------------------------------------
__global__ void __launch_bounds__(256) prep_kernel(const float* __restrict__ W) {
    extern __shared__ uint2 sb[];         // 32 rows x 192 uint2 chunks (4 bf16 each)
    __shared__ float sscale[32];
    int tid = threadIdx.x;
    int wid = tid >> 5;
    int lane = tid & 31;
    int v0 = blockIdx.x * 32;

    // --- merged zero of g_G / g_acc / g_done ---
    {
        int zb = blockIdx.x * 384;
        int z0 = zb + tid;
        if (z0 < DIM * DIM) g_G[z0] = 0.0f;
        int z1 = zb + 256 + tid;
        if (tid < 128 && z1 < DIM * DIM) g_G[z1] = 0.0f;
        if (blockIdx.x == 0 && tid < 2) g_acc[tid] = 0.0;
        if (blockIdx.x == 0 && tid == 2) g_done = 0u;
    }

    // --- phase 1: each warp loads 4 rows, computes sumsq, stages bf16 ---
    #pragma unroll
    for (int r = 0; r < 4; r++) {
        int vs = wid * 4 + r;
        int v = v0 + vs;
        float4 x[6];
        if (v < VOCAB) {
            const float4* rp = (const float4*)(W + (size_t)v * DIM);
            #pragma unroll
            for (int j = 0; j < 6; j++) x[j] = rp[lane + j * 32];
        } else {
            #pragma unroll
            for (int j = 0; j < 6; j++) x[j] = make_float4(0.f, 0.f, 0.f, 0.f);
        }
        float ssum = 0.0f;
        #pragma unroll
        for (int j = 0; j < 6; j++)
            ssum += x[j].x * x[j].x + x[j].y * x[j].y + x[j].z * x[j].z + x[j].w * x[j].w;
        #pragma unroll
        for (int off = 16; off; off >>= 1) ssum += __shfl_xor_sync(0xffffffffu, ssum, off);

        uint2* sv = sb + vs * 192;
        #pragma unroll
        for (int j = 0; j < 6; j++) {
            __nv_bfloat162 lo = __float22bfloat162_rn(make_float2(x[j].x, x[j].y));
            __nv_bfloat162 hi = __float22bfloat162_rn(make_float2(x[j].z, x[j].w));
            uint2 pk;
            pk.x = *(const uint32_t*)&lo;
            pk.y = *(const uint32_t*)&hi;
            int c = lane + j * 32;
            sv[c ^ vs] = pk;                    // XOR stays within each 32-chunk block
        }

        if (lane == 0) {
            float m = ssum * (1.0f / DIM) + EPS_F;
            sscale[vs] = rsqrtf(m);
            if (v < VOCAB) g_Diag[v] = ssum / m;   // = ||wn_v||^2
        }
    }
    __syncthreads();

    // --- phase 2: transposed scaled writes; lane <-> v, warp covers 24 chunks ---
    float sc = sscale[lane];
    const uint2* sl = sb + lane * 192;
    __nv_bfloat16* ocol = g_Wt + v0 + lane;
    #pragma unroll 4
    for (int c0 = 0; c0 < 24; c0++) {
        int chunk = wid * 24 + c0;
        uint2 pk = sl[chunk ^ lane];
        __nv_bfloat162 lo = *(const __nv_bfloat162*)&pk.x;
        __nv_bfloat162 hi = *(const __nv_bfloat162*)&pk.y;
        float2 f0 = __bfloat1622float2(lo);
        float2 f1 = __bfloat1622float2(hi);
        size_t d = (size_t)chunk * 4;
        ocol[(d + 0) * VPAD] = __float2bfloat16(f0.x * sc);
        ocol[(d + 1) * VPAD] = __float2bfloat16(f0.y * sc);
        ocol[(d + 2) * VPAD] = __float2bfloat16(f1.x * sc);
        ocol[(d + 3) * VPAD] = __float2bfloat16(f1.y * sc);
    }
}

// ---------------------------------------------------------------------------
// Kernel 2: bf16 Gram GEMM via mma.sync (m16n8k16).
// 3-stage cp.async pipeline (prefetch distance 2), 96KB smem -> 2 CTAs/SM
// (16 warps/SM fill tensor-pipe bubbles). CTA: one 128x128 tile (mi<=ni) x
// one of 14 K-splits. 8 warps, 64x32 each, single-buffered fragments.
// ---------------------------------------------------------------------------
__global__ void __launch_bounds__(256, 2) gram_kernel() {
    extern __shared__ char smem[];
    uint32_t sbase = smem_to_u32(smem);
    int tid = threadIdx.x;
    int wid = tid >> 5;
    int lane = tid & 31;

    // decode (mi, ni) with mi <= ni, and K split range
    int t = blockIdx.x % NPAIRS_T;
    int split = blockIdx.x / NPAIRS_T;
    int mi = 0;
    while (t >= NTILE - mi) { t -= NTILE - mi; mi++; }
    int ni = mi + t;
    int c0 = (split * KCHUNKS) / KSPLIT;
    int c1 = ((split + 1) * KCHUNKS) / KSPLIT;
    int nk = c1 - c0;

    const __nv_bfloat16* Abase = g_Wt + (size_t)(mi * 128) * VPAD;
    const __nv_bfloat16* Bbase = g_Wt + (size_t)(ni * 128) * VPAD;

    int ld_row = tid >> 3;          // 0..31 (+32 per i-iter)
    int ld_ch  = tid & 7;           // 16B chunk in 128B row

    float acc[4][4][4];
    #pragma unroll
    for (int a = 0; a < 4; a++)
        #pragma unroll
        for (int b = 0; b < 4; b++)
            #pragma unroll
            for (int c = 0; c < 4; c++) acc[a][b][c] = 0.0f;

    int warp_m = wid >> 2;          // 0..1
    int warp_n = wid & 3;           // 0..3
    int mbase = warp_m * 64;
    int nbase = warp_n * 32;
    int sub = lane >> 3;
    int r8  = lane & 7;

    // per-warp LDSM base offsets (within a stage buffer)
    uint32_t a_off[4], b_off[2];
    #pragma unroll
    for (int mt = 0; mt < 4; mt++) {
        int row = mbase + mt * 16 + (sub & 1) * 8 + r8;
        a_off[mt] = (uint32_t)row * 128 + (sub >> 1) * 16;
    }
    #pragma unroll
    for (int np = 0; np < 2; np++) {
        int row = nbase + np * 16 + (sub >> 1) * 8 + r8;
        b_off[np] = (uint32_t)row * 128 + (sub & 1) * 16;
    }

    // prologue: fill 2 stages (prefetch distance 2)
    #pragma unroll 1
    for (int s = 0; s < 2; s++) {
        if (s < nk) {
            uint32_t stA = sbase + s * STAGE_BYTES;
            uint32_t stB = stA + 16384;
            size_t kof = (size_t)(c0 + s) * KC + ld_ch * 8;
            #pragma unroll
            for (int i = 0; i < 4; i++) {
                int row = ld_row + i * 32;
                uint32_t d = swz((uint32_t)row * 128 + ld_ch * 16);
                cp_async16(stA + d, Abase + (size_t)row * VPAD + kof);
                cp_async16(stB + d, Bbase + (size_t)row * VPAD + kof);
            }
        }
        asm volatile("cp.async.commit_group;");
    }

    int buf = 0;
    #pragma unroll 1
    for (int it = 0; it < nk; it++) {
        // commits so far = it + 2; stage `it` is complete once <=1 group pending
        asm volatile("cp.async.wait_group 1;");
        __syncthreads();

        uint32_t stA = sbase + buf * STAGE_BYTES;
        uint32_t stB = stA + 16384;

        #pragma unroll
        for (int ks = 0; ks < 4; ks++) {
            uint32_t a[4][4], b[2][4];
            uint32_t kofs = (uint32_t)ks * 32;
            #pragma unroll
            for (int mt = 0; mt < 4; mt++) LDSM_X4(a[mt], stA + swz(a_off[mt] + kofs));
            #pragma unroll
            for (int np = 0; np < 2; np++) LDSM_X4(b[np], stB + swz(b_off[np] + kofs));
            #pragma unroll
            for (int mt = 0; mt < 4; mt++)
                #pragma unroll
                for (int nt = 0; nt < 4; nt++)
                    mma16816(acc[mt][nt], a[mt],
                             b[nt >> 1][(nt & 1) * 2], b[nt >> 1][(nt & 1) * 2 + 1]);
        }

        // prefetch stage it+2 into buffer (it+2)%3 == (it-1)%3 (freed last iter)
        if (it + 2 < nk) {
            int s = it + 2;
            int pb = buf + 2; if (pb >= 3) pb -= 3;
            uint32_t pA = sbase + pb * STAGE_BYTES;
            uint32_t pB = pA + 16384;
            size_t kof = (size_t)(c0 + s) * KC + ld_ch * 8;
            #pragma unroll
            for (int i = 0; i < 4; i++) {
                int row = ld_row + i * 32;
                uint32_t d = swz((uint32_t)row * 128 + ld_ch * 16);
                cp_async16(pA + d, Abase + (size_t)row * VPAD + kof);
                cp_async16(pB + d, Bbase + (size_t)row * VPAD + kof);
            }
        }
        asm volatile("cp.async.commit_group;");
        if (++buf == 3) buf = 0;
    }

    // epilogue: merge split-K partials into g_G
    int g = lane >> 2;
    int tt = lane & 3;
    #pragma unroll
    for (int mt = 0; mt < 4; mt++) {
        int m = mi * 128 + mbase + mt * 16 + g;
        #pragma unroll
        for (int nt = 0; nt < 4; nt++) {
            int n = ni * 128 + nbase + nt * 8 + tt * 2;
            float* p0 = g_G + (size_t)m * DIM + n;
            float* p1 = g_G + (size_t)(m + 8) * DIM + n;
            atomicAdd(p0 + 0, acc[mt][nt][0]);
            atomicAdd(p0 + 1, acc[mt][nt][1]);
            atomicAdd(p1 + 0, acc[mt][nt][2]);
            atomicAdd(p1 + 1, acc[mt][nt][3]);
        }
    }
}

// ---------------------------------------------------------------------------
// Kernel 3 (fused reduce+finalize): total_sq = sum over 768x768 of w*G^2
// (w=2 for off-diagonal tiles; lower tiles are zero), diag_sq = sum diag^2.
// Last block finalizes the scalar output.
// ---------------------------------------------------------------------------
__global__ void reduce_kernel(float* __restrict__ out) {
    const int n1 = DIM * DIM;
    const int tot = n1 + VOCAB;
    double accT = 0.0, accD = 0.0;
    for (int idx = blockIdx.x * 256 + threadIdx.x; idx < tot; idx += REDUCE_GRID * 256) {
        if (idx < n1) {
            int i = idx / DIM;
            int j = idx - i * DIM;
            double g = (double)g_G[idx];
            double w = ((i >> 7) == (j >> 7)) ? 1.0 : 2.0;
            accT += w * g * g;
        } else {
            double d = (double)g_Diag[idx - n1];
            accD += d * d;
        }
    }
    #pragma unroll
    for (int off = 16; off; off >>= 1) {
        accT += __shfl_xor_sync(0xffffffffu, accT, off);
        accD += __shfl_xor_sync(0xffffffffu, accD, off);
    }
    __shared__ double sT[8], sD[8];
    __shared__ bool is_last;
    if ((threadIdx.x & 31) == 0) { sT[threadIdx.x >> 5] = accT; sD[threadIdx.x >> 5] = accD; }
    __syncthreads();
    if (threadIdx.x == 0) {
        double tT = 0.0, tD = 0.0;
        #pragma unroll
        for (int i = 0; i < 8; i++) { tT += sT[i]; tD += sD[i]; }
        atomicAdd(&g_acc[0], tT);
        atomicAdd(&g_acc[1], tD);
        __threadfence();
        unsigned prev = atomicAdd(&g_done, 1u);
        is_last = (prev == REDUCE_GRID - 1);
    }
    __syncthreads();
    if (is_last && threadIdx.x == 0) {
        double n_pairs = (double)VOCAB * (double)(VOCAB - 1) * 0.5;
        out[0] = (float)((g_acc[0] - g_acc[1]) * 0.5 / n_pairs);
    }
}

// ---------------------------------------------------------------------------
// Launch
// ---------------------------------------------------------------------------
extern "C" void kernel_launch(void* const* d_in, const int* in_sizes, int n_in,
                              void* d_out, int out_size) {
    (void)in_sizes; (void)n_in; (void)out_size;
    const float* W = (const float*)d_in[0];
    float* out = (float*)d_out;

    cudaFuncSetAttribute(prep_kernel, cudaFuncAttributeMaxDynamicSharedMemorySize, PREP_SMEM);
    cudaFuncSetAttribute(gram_kernel, cudaFuncAttributeMaxDynamicSharedMemorySize, SMEM_K3);

    prep_kernel<<<VPAD / 32, 256, PREP_SMEM>>>(W);
    gram_kernel<<<NPAIRS_T * KSPLIT, 256, SMEM_K3>>>();
    reduce_kernel<<<REDUCE_GRID, 256>>>(out);
}

// round 11
// speedup vs baseline: 1.7724x; 1.0588x over previous
#include <cuda_runtime.h>
#include <cuda_bf16.h>
#include <cstdint>

// ---------------------------------------------------------------------------
// Problem constants
// ---------------------------------------------------------------------------
#define VOCAB 50257
#define DIM   768
#define VPAD  50304            // ceil(VOCAB/128)*128 = 393*128
#define NTILE 6                // 768 / 128
#define NPAIRS_T 21            // upper-triangle 128x128 tiles (mi<=ni)
#define KSPLIT 14              // split-K -> 21*14 = 294 CTAs (2 per SM)
#define EPS_F 1.1920929e-7f    // jnp.finfo(float32).eps

#define KC 64                  // K (vocab) elements per pipeline stage
#define KCHUNKS (VPAD / KC)    // 786
#define STAGE_BYTES 32768      // A tile 16KB + B tile 16KB (64 rows x 256B each)
#define NSTAGES 3
#define SMEM_K3 (NSTAGES * STAGE_BYTES)   // 96KB -> 2 CTAs/SM

#define REDUCE_GRID 256

// ---------------------------------------------------------------------------
// Device scratch (allocation-free: __device__ globals)
// ---------------------------------------------------------------------------
__device__ __align__(16) __nv_bfloat16 g_Wn[(size_t)VPAD * DIM];  // Wn, bf16, v-major
__device__ float  g_Diag[VOCAB];
__device__ float  g_G[DIM * DIM];                    // Gram accumulator (upper tiles)
__device__ double g_acc[2];                          // [0]=total_sq, [1]=diag_sq
__device__ unsigned g_done;                          // last-block flag for fused finalize

// ---------------------------------------------------------------------------
// PTX helpers (family-portable: cp.async / ldmatrix / mma.sync only)
// ---------------------------------------------------------------------------
__device__ __forceinline__ uint32_t smem_to_u32(const void* p) {
    uint32_t a;
    asm("{ .reg .u64 t; cvta.to.shared.u64 t, %1; cvt.u32.u64 %0, t; }" : "=r"(a) : "l"(p));
    return a;
}

__device__ __forceinline__ void cp_async16(uint32_t dst, const void* src) {
    asm volatile("cp.async.cg.shared.global [%0], [%1], 16;" :: "r"(dst), "l"(src));
}

// transposed ldmatrix: smem tile is [k][m] / [k][n]; fragments come out as
// the mma.row.col A/B layouts.
#define LDSM_X4T(r, addr) \
    asm volatile("ldmatrix.sync.aligned.m8n8.x4.trans.shared.b16 {%0,%1,%2,%3}, [%4];" \
        : "=r"((r)[0]), "=r"((r)[1]), "=r"((r)[2]), "=r"((r)[3]) : "r"(addr))

__device__ __forceinline__ void mma16816(float* c, const uint32_t* a, uint32_t b0, uint32_t b1) {
    asm volatile(
        "mma.sync.aligned.m16n8k16.row.col.f32.bf16.bf16.f32 "
        "{%0,%1,%2,%3}, {%4,%5,%6,%7}, {%8,%9}, {%0,%1,%2,%3};"
        : "+f"(c[0]), "+f"(c[1]), "+f"(c[2]), "+f"(c[3])
        : "r"(a[0]), "r"(a[1]), "r"(a[2]), "r"(a[3]), "r"(b0), "r"(b1));
}

// swizzle for 256B smem rows: XOR 16B-chunk bits[6:4] with row bits[10:8]
__device__ __forceinline__ uint32_t swz256(uint32_t off) { return off ^ ((off >> 4) & 0x70); }

// ---------------------------------------------------------------------------
// Kernel 1 (streaming prep): row stats + scale + bf16 quantize, row-major out.
// One warp per vocab row; fully-coalesced fp32 reads and 8B bf16 stores.
// Also zeroes g_G / g_acc / g_done (blocks 0..2303 cover g_G).
// ---------------------------------------------------------------------------
__global__ void __launch_bounds__(256) prep_kernel(const float* __restrict__ W) {
    int tid = threadIdx.x;
    int wid = tid >> 5;
    int lane = tid & 31;

    // merged zero of scratch
    {
        int zi = blockIdx.x * 256 + tid;
        if (zi < DIM * DIM) g_G[zi] = 0.0f;
        if (blockIdx.x == 0 && tid < 2) g_acc[tid] = 0.0;
        if (blockIdx.x == 0 && tid == 2) g_done = 0u;
    }

    int v = blockIdx.x * 8 + wid;          // grid = VPAD/8
    float4 x[6];
    if (v < VOCAB) {
        const float4* rp = (const float4*)(W + (size_t)v * DIM);
        #pragma unroll
        for (int j = 0; j < 6; j++) x[j] = rp[lane + j * 32];
    } else {
        #pragma unroll
        for (int j = 0; j < 6; j++) x[j] = make_float4(0.f, 0.f, 0.f, 0.f);
    }
    float ssum = 0.0f;
    #pragma unroll
    for (int j = 0; j < 6; j++)
        ssum += x[j].x * x[j].x + x[j].y * x[j].y + x[j].z * x[j].z + x[j].w * x[j].w;
    #pragma unroll
    for (int off = 16; off; off >>= 1) ssum += __shfl_xor_sync(0xffffffffu, ssum, off);

    float m = ssum * (1.0f / DIM) + EPS_F;
    float sc = rsqrtf(m);
    if (lane == 0 && v < VOCAB) g_Diag[v] = ssum / m;   // = ||wn_v||^2

    uint2* orow = (uint2*)(g_Wn + (size_t)v * DIM);
    #pragma unroll
    for (int j = 0; j < 6; j++) {
        __nv_bfloat162 lo = __float22bfloat162_rn(make_float2(x[j].x * sc, x[j].y * sc));
        __nv_bfloat162 hi = __float22bfloat162_rn(make_float2(x[j].z * sc, x[j].w * sc));
        uint2 pk;
        pk.x = *(const uint32_t*)&lo;
        pk.y = *(const uint32_t*)&hi;
        orow[lane + j * 32] = pk;
    }
}

// ---------------------------------------------------------------------------
// Kernel 2: bf16 Gram GEMM via mma.sync (m16n8k16) + ldmatrix.trans.
// Smem tiles are k-major ([64 k][128 m] / [64 k][128 n], 256B rows, swizzled).
// 3-stage cp.async pipeline (prefetch distance 2), 96KB smem -> 2 CTAs/SM.
// CTA: one 128x128 tile (mi<=ni) x one of 14 K-splits. 8 warps, 64x32 each.
// ---------------------------------------------------------------------------
__global__ void __launch_bounds__(256, 2) gram_kernel() {
    extern __shared__ char smem[];
    uint32_t sbase = smem_to_u32(smem);
    int tid = threadIdx.x;
    int wid = tid >> 5;
    int lane = tid & 31;

    // decode (mi, ni) with mi <= ni, and K split range
    int t = blockIdx.x % NPAIRS_T;
    int split = blockIdx.x / NPAIRS_T;
    int mi = 0;
    while (t >= NTILE - mi) { t -= NTILE - mi; mi++; }
    int ni = mi + t;
    int c0 = (split * KCHUNKS) / KSPLIT;
    int c1 = ((split + 1) * KCHUNKS) / KSPLIT;
    int nk = c1 - c0;

    // gmem element offsets within a Wn row for each panel
    const int moff = mi * 128;
    const int noff = ni * 128;

    // cp.async thread assignment: row = tid>>4 (+16/iter), chunk = tid&15
    int ld_row = tid >> 4;          // 0..15
    int ld_ch  = tid & 15;          // 16B chunk within 256B row

    float acc[4][4][4];
    #pragma unroll
    for (int a = 0; a < 4; a++)
        #pragma unroll
        for (int b = 0; b < 4; b++)
            #pragma unroll
            for (int c = 0; c < 4; c++) acc[a][b][c] = 0.0f;

    int warp_m = wid >> 2;          // 0..1
    int warp_n = wid & 3;           // 0..3
    int mbase = warp_m * 64;
    int nbase = warp_n * 32;
    int sub = lane >> 3;
    int r8  = lane & 7;

    // per-warp LDSM offsets within a stage tile (k-major, swizzled).
    // A matrices: sub -> (m-octet = sub&1, k-octet = sub>>1)
    uint32_t a_off[4];
    #pragma unroll
    for (int mt = 0; mt < 4; mt++) {
        int mcol = mbase + mt * 16 + (sub & 1) * 8;     // m start of 8-col block
        int ch = mcol >> 3;                              // 16B chunk index
        a_off[mt] = (uint32_t)(((sub >> 1) * 8 + r8) * 256) + (uint32_t)((ch ^ r8) * 16);
    }
    // B matrices: sub -> (k-octet = sub&1, n-octet = sub>>1)
    uint32_t b_off[2];
    #pragma unroll
    for (int np = 0; np < 2; np++) {
        int ncol = nbase + np * 16 + (sub >> 1) * 8;
        int ch = ncol >> 3;
        b_off[np] = (uint32_t)(((sub & 1) * 8 + r8) * 256) + (uint32_t)((ch ^ r8) * 16);
    }

    // prologue: fill 2 stages (prefetch distance 2)
    #pragma unroll 1
    for (int s = 0; s < 2; s++) {
        if (s < nk) {
            uint32_t stA = sbase + s * STAGE_BYTES;
            uint32_t stB = stA + 16384;
            size_t kbase = (size_t)(c0 + s) * KC;
            #pragma unroll
            for (int i = 0; i < 4; i++) {
                int row = ld_row + i * 16;
                uint32_t d = (uint32_t)row * 256 + (uint32_t)((ld_ch ^ (row & 7)) * 16);
                const __nv_bfloat16* src = g_Wn + (kbase + row) * DIM + ld_ch * 8;
                cp_async16(stA + d, src + moff);
                cp_async16(stB + d, src + noff);
            }
        }
        asm volatile("cp.async.commit_group;");
    }

    int buf = 0;
    #pragma unroll 1
    for (int it = 0; it < nk; it++) {
        // commits so far = it + 2; stage `it` is complete once <=1 group pending
        asm volatile("cp.async.wait_group 1;");
        __syncthreads();

        uint32_t stA = sbase + buf * STAGE_BYTES;
        uint32_t stB = stA + 16384;

        #pragma unroll
        for (int ks = 0; ks < 4; ks++) {
            uint32_t a[4][4], b[2][4];
            uint32_t kofs = (uint32_t)ks * 4096;    // 16 k-rows * 256B
            #pragma unroll
            for (int mt = 0; mt < 4; mt++) LDSM_X4T(a[mt], stA + a_off[mt] + kofs);
            #pragma unroll
            for (int np = 0; np < 2; np++) LDSM_X4T(b[np], stB + b_off[np] + kofs);
            #pragma unroll
            for (int mt = 0; mt < 4; mt++)
                #pragma unroll
                for (int nt = 0; nt < 4; nt++)
                    mma16816(acc[mt][nt], a[mt],
                             b[nt >> 1][(nt & 1) * 2], b[nt >> 1][(nt & 1) * 2 + 1]);
        }

        // prefetch stage it+2 into buffer (buf+2)%3 (freed last iter)
        if (it + 2 < nk) {
            int s = it + 2;
            int pb = buf + 2; if (pb >= 3) pb -= 3;
            uint32_t pA = sbase + pb * STAGE_BYTES;
            uint32_t pB = pA + 16384;
            size_t kbase = (size_t)(c0 + s) * KC;
            #pragma unroll
            for (int i = 0; i < 4; i++) {
                int row = ld_row + i * 16;
                uint32_t d = (uint32_t)row * 256 + (uint32_t)((ld_ch ^ (row & 7)) * 16);
                const __nv_bfloat16* src = g_Wn + (kbase + row) * DIM + ld_ch * 8;
                cp_async16(pA + d, src + moff);
                cp_async16(pB + d, src + noff);
            }
        }
        asm volatile("cp.async.commit_group;");
        if (++buf == 3) buf = 0;
    }

    // epilogue: merge split-K partials into g_G
    int g = lane >> 2;
    int tt = lane & 3;
    #pragma unroll
    for (int mt = 0; mt < 4; mt++) {
        int m = mi * 128 + mbase + mt * 16 + g;
        #pragma unroll
        for (int nt = 0; nt < 4; nt++) {
            int n = ni * 128 + nbase + nt * 8 + tt * 2;
            float* p0 = g_G + (size_t)m * DIM + n;
            float* p1 = g_G + (size_t)(m + 8) * DIM + n;
            atomicAdd(p0 + 0, acc[mt][nt][0]);
            atomicAdd(p0 + 1, acc[mt][nt][1]);
            atomicAdd(p1 + 0, acc[mt][nt][2]);
            atomicAdd(p1 + 1, acc[mt][nt][3]);
        }
    }
}

// ---------------------------------------------------------------------------
// Kernel 3 (fused reduce+finalize): total_sq = sum over 768x768 of w*G^2
// (w=2 for off-diagonal tiles; lower tiles are zero), diag_sq = sum diag^2.
// Last block finalizes the scalar output.
// ---------------------------------------------------------------------------
__global__ void reduce_kernel(float* __restrict__ out) {
    const int n1 = DIM * DIM;
    const int tot = n1 + VOCAB;
    double accT = 0.0, accD = 0.0;
    for (int idx = blockIdx.x * 256 + threadIdx.x; idx < tot; idx += REDUCE_GRID * 256) {
        if (idx < n1) {
            int i = idx / DIM;
            int j = idx - i * DIM;
            double g = (double)g_G[idx];
            double w = ((i >> 7) == (j >> 7)) ? 1.0 : 2.0;
            accT += w * g * g;
        } else {
            double d = (double)g_Diag[idx - n1];
            accD += d * d;
        }
    }
    #pragma unroll
    for (int off = 16; off; off >>= 1) {
        accT += __shfl_xor_sync(0xffffffffu, accT, off);
        accD += __shfl_xor_sync(0xffffffffu, accD, off);
    }
    __shared__ double sT[8], sD[8];
    __shared__ bool is_last;
    if ((threadIdx.x & 31) == 0) { sT[threadIdx.x >> 5] = accT; sD[threadIdx.x >> 5] = accD; }
    __syncthreads();
    if (threadIdx.x == 0) {
        double tT = 0.0, tD = 0.0;
        #pragma unroll
        for (int i = 0; i < 8; i++) { tT += sT[i]; tD += sD[i]; }
        atomicAdd(&g_acc[0], tT);
        atomicAdd(&g_acc[1], tD);
        __threadfence();
        unsigned prev = atomicAdd(&g_done, 1u);
        is_last = (prev == REDUCE_GRID - 1);
    }
    __syncthreads();
    if (is_last && threadIdx.x == 0) {
        double n_pairs = (double)VOCAB * (double)(VOCAB - 1) * 0.5;
        out[0] = (float)((g_acc[0] - g_acc[1]) * 0.5 / n_pairs);
    }
}

// ---------------------------------------------------------------------------
// Launch
// ---------------------------------------------------------------------------
extern "C" void kernel_launch(void* const* d_in, const int* in_sizes, int n_in,
                              void* d_out, int out_size) {
    (void)in_sizes; (void)n_in; (void)out_size;
    const float* W = (const float*)d_in[0];
    float* out = (float*)d_out;

    cudaFuncSetAttribute(gram_kernel, cudaFuncAttributeMaxDynamicSharedMemorySize, SMEM_K3);

    prep_kernel<<<VPAD / 8, 256>>>(W);
    gram_kernel<<<NPAIRS_T * KSPLIT, 256, SMEM_K3>>>();
    reduce_kernel<<<REDUCE_GRID, 256>>>(out);
}